// round 6
// baseline (speedup 1.0000x reference)
#include <cuda_runtime.h>
#include <cstdint>

// ChamferDistance on GB300 — persistent balanced single-wave version.
// Inner math identical to Round 5 (f32x2 FFMA packed over the reference axis,
// SoA smem tile, queries pre-duplicated {q,q} scaled by -2).
// All work flattened into uniform 256-ref tiles; each CTA takes a contiguous
// block of tiles (ref-tile fastest-varying), keeps row minima in registers
// across tiles of the same row-group, and flushes via uint atomicMin.

#define CD_THREADS 256
#define CD_P       4      // query points per thread  -> 1024 rows per row-group
#define CD_TILE    256    // reference points per tile
#define CD_OCC     3      // CTAs per SM

__device__ __forceinline__ uint64_t cd_dup2(float v) {
    uint64_t r;
    asm("mov.b64 %0, {%1, %1};" : "=l"(r) : "r"(__float_as_uint(v)));
    return r;
}

// {dlo,dhi} = qx*px + (qy*py + (qz*pz + s)) lane-wise over 2 ref points.
__device__ __forceinline__ void cd_dot2(uint64_t qx, uint64_t qy, uint64_t qz,
                                        uint64_t px, uint64_t py, uint64_t pz,
                                        uint64_t s,
                                        float& dlo, float& dhi) {
    uint32_t lo, hi;
    asm("{\n\t"
        ".reg .b64 t;\n\t"
        "fma.rn.f32x2 t, %2, %3, %4;\n\t"
        "fma.rn.f32x2 t, %5, %6, t;\n\t"
        "fma.rn.f32x2 t, %7, %8, t;\n\t"
        "mov.b64 {%0, %1}, t;\n\t"
        "}"
        : "=r"(lo), "=r"(hi)
        : "l"(qz), "l"(pz), "l"(s),
          "l"(qy), "l"(py),
          "l"(qx), "l"(px));
    dlo = __uint_as_float(lo);
    dhi = __uint_as_float(hi);
}

__global__ void cd_init_out(unsigned* __restrict__ out, int n) {
    int i = blockIdx.x * blockDim.x + threadIdx.x;
    if (i < n) out[i] = 0x7F800000u;   // +inf
}

__global__ __launch_bounds__(CD_THREADS, CD_OCC)
void chamfer_persist_kernel(const float* __restrict__ xyz1,
                            const float* __restrict__ xyz2,
                            float* __restrict__ out,
                            int N, int M, int B,
                            int nItems, int itemsPerCta)
{
    const int start = blockIdx.x * itemsPerCta;
    int end = start + itemsPerCta;
    if (end > nItems) end = nItems;
    if (start >= end) return;

    const int tid = threadIdx.x;

    // Item layout: it = g * tilesPer + t, t = ref tile (fastest varying).
    // g = ((dir * B) + b) * rowBlocks + rowblk.   (N == M assumed; true here.)
    const int rowBlocks = N / (CD_THREADS * CD_P);   // 8
    const int tilesPer  = M / CD_TILE;               // 32

    __shared__ float sx[CD_TILE];
    __shared__ float sy[CD_TILE];
    __shared__ float sz[CD_TILE];
    __shared__ float ss[CD_TILE];

    // Per-row-group state (valid while curG unchanged)
    uint64_t qxd[CD_P], qyd[CD_P], qzd[CD_P];
    float sq1[CD_P], m[CD_P];
    const float* rb = nullptr;
    float*       ob = nullptr;
    int Nq = 0, Nr = 0, row0 = 0;
    int curG = -1;

    for (int it = start; it < end; ++it) {
        const int g = it / tilesPer;
        const int t = it - g * tilesPer;

        if (g != curG) {
            // Flush previous row-group's minima
            if (curG >= 0) {
                #pragma unroll
                for (int p = 0; p < CD_P; p++) {
                    int rw = row0 + p * CD_THREADS + tid;
                    if (rw < Nq) {
                        float d = fmaxf(m[p] + sq1[p], 0.0f);
                        atomicMin((unsigned*)&ob[rw], __float_as_uint(d));
                    }
                }
            }
            curG = g;
            int rem    = g % (B * rowBlocks);
            int dir    = g / (B * rowBlocks);
            int b      = rem / rowBlocks;
            int rowblk = rem - b * rowBlocks;

            const float* q = (dir == 0) ? xyz1 : xyz2;
            const float* r = (dir == 0) ? xyz2 : xyz1;
            Nq = (dir == 0) ? N : M;
            Nr = (dir == 0) ? M : N;
            ob = out + ((dir == 0) ? 0 : (size_t)B * N) + (size_t)b * Nq;
            rb = r + (size_t)b * Nr * 3;
            const float* qb = q + (size_t)b * Nq * 3;
            row0 = rowblk * (CD_THREADS * CD_P);

            #pragma unroll
            for (int p = 0; p < CD_P; p++) {
                int rw = row0 + p * CD_THREADS + tid;
                int rr = (rw < Nq) ? rw : 0;
                float x = qb[(size_t)rr * 3 + 0];
                float y = qb[(size_t)rr * 3 + 1];
                float z = qb[(size_t)rr * 3 + 2];
                sq1[p] = fmaf(x, x, fmaf(y, y, z * z));
                qxd[p] = cd_dup2(-2.0f * x);
                qyd[p] = cd_dup2(-2.0f * y);
                qzd[p] = cd_dup2(-2.0f * z);
                m[p] = 3.402823466e+38f;
            }
        }

        // Stage this tile (256 refs) in SoA smem
        const int base = t * CD_TILE;
        __syncthreads();   // previous tile's readers done before overwrite
        {
            int j = base + tid;
            float x = 0.f, y = 0.f, z = 0.f, s = 3.402823466e+38f;
            if (j < Nr) {
                x = rb[(size_t)j * 3 + 0];
                y = rb[(size_t)j * 3 + 1];
                z = rb[(size_t)j * 3 + 2];
                s = fmaf(x, x, fmaf(y, y, z * z));
            }
            sx[tid] = x; sy[tid] = y; sz[tid] = z; ss[tid] = s;
        }
        __syncthreads();

        const uint64_t* __restrict__ px2 = (const uint64_t*)sx;
        const uint64_t* __restrict__ py2 = (const uint64_t*)sy;
        const uint64_t* __restrict__ pz2 = (const uint64_t*)sz;
        const uint64_t* __restrict__ ps2 = (const uint64_t*)ss;

        #pragma unroll 2
        for (int jj = 0; jj < CD_TILE / 2; jj++) {
            uint64_t px = px2[jj];   // {x_j, x_j+1} broadcast, conflict-free
            uint64_t py = py2[jj];
            uint64_t pz = pz2[jj];
            uint64_t ps = ps2[jj];
            #pragma unroll
            for (int p = 0; p < CD_P; p++) {
                float dlo, dhi;
                cd_dot2(qxd[p], qyd[p], qzd[p], px, py, pz, ps, dlo, dhi);
                m[p] = fminf(m[p], fminf(dlo, dhi));
            }
        }
    }

    // Final flush
    if (curG >= 0) {
        #pragma unroll
        for (int p = 0; p < CD_P; p++) {
            int rw = row0 + p * CD_THREADS + tid;
            if (rw < Nq) {
                float d = fmaxf(m[p] + sq1[p], 0.0f);
                atomicMin((unsigned*)&ob[rw], __float_as_uint(d));
            }
        }
    }
}

extern "C" void kernel_launch(void* const* d_in, const int* in_sizes, int n_in,
                              void* d_out, int out_size)
{
    const float* xyz1 = (const float*)d_in[0];
    const float* xyz2 = (const float*)d_in[1];
    float* out = (float*)d_out;

    const int B = 8;
    const int N = (in_sizes[0] / 3) / B;   // 8192
    const int M = (in_sizes[1] / 3) / B;   // 8192

    // Output must start at +inf for atomicMin combining.
    cd_init_out<<<(out_size + 255) / 256, 256>>>((unsigned*)out, out_size);

    // Persistent single wave: exactly CD_OCC CTAs per SM.
    int dev = 0, sms = 148;
    cudaGetDevice(&dev);
    cudaDeviceGetAttribute(&sms, cudaDevAttrMultiProcessorCount, dev);
    int nCta = sms * CD_OCC;

    const int rowBlocks = N / (CD_THREADS * CD_P);         // 8
    const int tilesPer  = M / CD_TILE;                     // 32
    const int nItems    = 2 * B * rowBlocks * tilesPer;    // 4096
    const int ipc       = (nItems + nCta - 1) / nCta;      // 9 @ 456 CTAs

    chamfer_persist_kernel<<<nCta, CD_THREADS>>>(xyz1, xyz2, out,
                                                 N, M, B, nItems, ipc);
}

// round 8
// speedup vs baseline: 1.0115x; 1.0115x over previous
#include <cuda_runtime.h>
#include <cstdint>

// ChamferDistance on GB300 — Round 8.
// Round 5 config (best) + LDS.128 SoA tile loads (4 refs/instr) + scalar
// 2-level min tree (1 FMNMX per pair). f32x2 FFMA dot unchanged.

#define CD_THREADS 256
#define CD_P       4      // query points per thread
#define CD_TILE    256    // reference points staged in smem per step
#define CD_SPLIT   8      // reference-dimension split

__device__ __forceinline__ uint64_t cd_dup2(float v) {
    uint64_t r;
    asm("mov.b64 %0, {%1, %1};" : "=l"(r) : "r"(__float_as_uint(v)));
    return r;
}

// {dlo,dhi} = qx*px + (qy*py + (qz*pz + s)) lane-wise over 2 packed refs.
__device__ __forceinline__ void cd_dot2(uint64_t qx, uint64_t qy, uint64_t qz,
                                        uint64_t px, uint64_t py, uint64_t pz,
                                        uint64_t s,
                                        float& dlo, float& dhi) {
    uint32_t lo, hi;
    asm("{\n\t"
        ".reg .b64 t;\n\t"
        "fma.rn.f32x2 t, %2, %3, %4;\n\t"
        "fma.rn.f32x2 t, %5, %6, t;\n\t"
        "fma.rn.f32x2 t, %7, %8, t;\n\t"
        "mov.b64 {%0, %1}, t;\n\t"
        "}"
        : "=r"(lo), "=r"(hi)
        : "l"(qz), "l"(pz), "l"(s),
          "l"(qy), "l"(py),
          "l"(qx), "l"(px));
    dlo = __uint_as_float(lo);
    dhi = __uint_as_float(hi);
}

__global__ void cd_init_out(unsigned* __restrict__ out, int n) {
    int i = blockIdx.x * blockDim.x + threadIdx.x;
    if (i < n) out[i] = 0x7F800000u;   // +inf
}

__global__ __launch_bounds__(CD_THREADS, 3)
void chamfer_min_kernel(const float* __restrict__ xyz1,
                        const float* __restrict__ xyz2,
                        float* __restrict__ out,
                        int N, int M, int B)
{
    const int zz    = blockIdx.z;
    const int dir   = zz / CD_SPLIT;      // 0: q=xyz1 vs r=xyz2 ; 1: swapped
    const int split = zz % CD_SPLIT;
    const int b     = blockIdx.y;

    const float* __restrict__ q = (dir == 0) ? xyz1 : xyz2;
    const float* __restrict__ r = (dir == 0) ? xyz2 : xyz1;
    const int Nq = (dir == 0) ? N : M;
    const int Nr = (dir == 0) ? M : N;
    float* __restrict__ o = out + ((dir == 0) ? 0 : (size_t)B * N);

    const float* __restrict__ qb = q + (size_t)b * Nq * 3;
    const float* __restrict__ rb = r + (size_t)b * Nr * 3;

    const int chunk = (Nr + CD_SPLIT - 1) / CD_SPLIT;
    const int r0 = split * chunk;
    const int r1 = (r0 + chunk < Nr) ? (r0 + chunk) : Nr;

    const int tid = threadIdx.x;
    const int row0 = blockIdx.x * (CD_THREADS * CD_P);

    // Loop-invariant duplicated query packs, coords pre-scaled by -2.
    uint64_t qxd[CD_P], qyd[CD_P], qzd[CD_P];
    float sq1[CD_P], m[CD_P];
    #pragma unroll
    for (int p = 0; p < CD_P; p++) {
        int rw = row0 + p * CD_THREADS + tid;
        int rr = (rw < Nq) ? rw : 0;
        float x = qb[(size_t)rr * 3 + 0];
        float y = qb[(size_t)rr * 3 + 1];
        float z = qb[(size_t)rr * 3 + 2];
        sq1[p] = fmaf(x, x, fmaf(y, y, z * z));
        qxd[p] = cd_dup2(-2.0f * x);
        qyd[p] = cd_dup2(-2.0f * y);
        qzd[p] = cd_dup2(-2.0f * z);
        m[p] = 3.402823466e+38f;
    }

    // SoA tile, 16B-aligned so ulonglong2 loads are LDS.128 (4 refs/instr).
    __shared__ __align__(16) float sx[CD_TILE];
    __shared__ __align__(16) float sy[CD_TILE];
    __shared__ __align__(16) float sz[CD_TILE];
    __shared__ __align__(16) float ss[CD_TILE];

    for (int base = r0; base < r1; base += CD_TILE) {
        {
            int j = base + tid;
            float x = 0.f, y = 0.f, z = 0.f, s = 3.402823466e+38f;
            if (j < r1) {
                x = rb[(size_t)j * 3 + 0];
                y = rb[(size_t)j * 3 + 1];
                z = rb[(size_t)j * 3 + 2];
                s = fmaf(x, x, fmaf(y, y, z * z));
            }
            sx[tid] = x; sy[tid] = y; sz[tid] = z; ss[tid] = s;
        }
        __syncthreads();

        const ulonglong2* __restrict__ px4 = (const ulonglong2*)sx;
        const ulonglong2* __restrict__ py4 = (const ulonglong2*)sy;
        const ulonglong2* __restrict__ pz4 = (const ulonglong2*)sz;
        const ulonglong2* __restrict__ ps4 = (const ulonglong2*)ss;

        #pragma unroll 2
        for (int j4 = 0; j4 < CD_TILE / 4; j4++) {
            ulonglong2 X = px4[j4];   // {x_j,x_j+1},{x_j+2,x_j+3} broadcast
            ulonglong2 Y = py4[j4];
            ulonglong2 Z = pz4[j4];
            ulonglong2 S = ps4[j4];
            #pragma unroll
            for (int p = 0; p < CD_P; p++) {
                float a0, a1, b0, b1;
                cd_dot2(qxd[p], qyd[p], qzd[p], X.x, Y.x, Z.x, S.x, a0, a1);
                cd_dot2(qxd[p], qyd[p], qzd[p], X.y, Y.y, Z.y, S.y, b0, b1);
                // 2-level min tree: 4 FMNMX per 4 refs (1 per pair)
                float e = fminf(a0, b0);
                float f = fminf(a1, b1);
                m[p] = fminf(m[p], fminf(e, f));
            }
        }
        __syncthreads();
    }

    #pragma unroll
    for (int p = 0; p < CD_P; p++) {
        int rw = row0 + p * CD_THREADS + tid;
        if (rw < Nq) {
            float d = fmaxf(m[p] + sq1[p], 0.0f);   // non-negative -> uint order
            atomicMin((unsigned*)&o[(size_t)b * Nq + rw], __float_as_uint(d));
        }
    }
}

extern "C" void kernel_launch(void* const* d_in, const int* in_sizes, int n_in,
                              void* d_out, int out_size)
{
    const float* xyz1 = (const float*)d_in[0];
    const float* xyz2 = (const float*)d_in[1];
    float* out = (float*)d_out;

    const int B = 8;
    const int N = (in_sizes[0] / 3) / B;   // 8192
    const int M = (in_sizes[1] / 3) / B;   // 8192

    // Output must start at +inf for atomicMin combining.
    cd_init_out<<<(out_size + 255) / 256, 256>>>((unsigned*)out, out_size);

    int rows_per_block = CD_THREADS * CD_P;              // 1024
    int gx = (N + rows_per_block - 1) / rows_per_block;  // 8

    dim3 grid(gx, B, 2 * CD_SPLIT);                      // 8 x 8 x 16 = 1024 blocks
    dim3 block(CD_THREADS);
    chamfer_min_kernel<<<grid, block>>>(xyz1, xyz2, out, N, M, B);
}